// round 10
// baseline (speedup 1.0000x reference)
#include <cuda_runtime.h>
#include <cstdint>

// Shapes (fixed): B=128, CIN=16, COUT=16, F=512, N=32, K=2
#define BB   128
#define CI   16
#define CO   16
#define FF   512
#define NN   32
#define NTILES ((BB * FF) / 16)   // 4096 tiles of 16 (b,f)-rows
#define GRID   304                // 2 persistent blocks / SM

// smem: sW [i][c][n] packed (k0,k1) = 64 KB ; sBP [c][n] packed (bv,bv) = 4 KB
#define SW_CNT   (CI * CO * NN)
#define SMEM_BYTES (SW_CNT * 8 + CO * NN * 8)

__device__ __forceinline__ uint64_t pack2(float lo, float hi) {
    uint64_t r;
    asm("mov.b64 %0, {%1, %2};" : "=l"(r) : "f"(lo), "f"(hi));
    return r;
}
__device__ __forceinline__ void ffma2(uint64_t& acc, uint64_t a, uint64_t b) {
    asm("fma.rn.f32x2 %0, %1, %2, %0;" : "+l"(acc) : "l"(a), "l"(b));
}
__device__ __forceinline__ void stcs64(uint64_t* p, uint64_t v) {
    asm volatile("st.global.cs.b64 [%0], %1;" :: "l"(p), "l"(v) : "memory");
}

__global__ __launch_bounds__(256, 2)
void up_kernel(const float* __restrict__ x,
               const float* __restrict__ W1, const float* __restrict__ b1,
               const float* __restrict__ W2, const float* __restrict__ b2,
               float* __restrict__ out)
{
    extern __shared__ uint64_t sW[];
    uint64_t* sBP = sW + SW_CNT;

    const int tid = threadIdx.x;

    // ---- register-LIGHT fused fold: one (i,c,n) element per iteration ----
    // (the per-element body keeps ~12 live regs; outer loop NOT unrolled so
    //  ptxas can't batch 32 elements' loads into a huge live set)
#pragma unroll 1
    for (int e = 0; e < SW_CNT / 256; ++e) {
        const int idx = tid + e * 256;
        const int n = idx & 31;
        const int c = (idx >> 5) & 15;
        const int i = idx >> 9;
        float s0 = 0.f, s1 = 0.f;
        const float2* w1 = (const float2*)(W1 + ((size_t)(n * CI + i) * CO) * 2);
        const float*  w2 = W2 + (size_t)n * CO * CO + c;
#pragma unroll
        for (int o = 0; o < CO; ++o) {
            float2 a  = __ldg(w1 + o);
            float  wv = __ldg(w2 + o * CO);
            s0 = fmaf(a.x, wv, s0);
            s1 = fmaf(a.y, wv, s1);
        }
        sW[(i * CO + c) * NN + n] = pack2(s0, s1);
    }
#pragma unroll 1
    for (int e = 0; e < 2; ++e) {            // CO*NN = 512 bias entries
        const int idx = tid + e * 256;
        const int n = idx & 31;
        const int c = idx >> 5;
        float s = __ldg(b2 + n * CO + c);
#pragma unroll
        for (int o = 0; o < CO; ++o)
            s = fmaf(__ldg(b1 + n * CO + o),
                     __ldg(W2 + (size_t)(n * CO + o) * CO + c), s);
        sBP[c * NN + n] = pack2(s, s);
    }
    __syncthreads();

    // ---- R2's proven main body (R=8 rows, Cw=4 channels, 16 warps/SM) ----
    const int lane = tid & 31;           // n
    const int warp = tid >> 5;
    const int c0   = (warp & 3) * 4;     // 4 channels per warp
    const int g    = warp >> 2;          // row half (rows g*8 .. g*8+7)

    uint64_t bp[4];
#pragma unroll
    for (int cc = 0; cc < 4; ++cc)
        bp[cc] = sBP[(c0 + cc) * NN + lane];

    const uint64_t* wbase = sW + c0 * NN + lane;
    const int bx = blockIdx.x;

    // 32-bit x offsets (x has 33.5M floats < 2^31)
    uint32_t xoff;
    {
        const uint32_t rb = (uint32_t)bx * 16 + g * 8;
        xoff = ((rb >> 9) * (CI * FF) + (rb & (FF - 1))) * NN + lane;
    }

    // double buffer, pre-packed u64; 16 i-steps/tile (even) -> parity
    // tile-invariant: slot 0 holds i=0 at every tile entry.
    uint64_t xv[2][8];
#pragma unroll
    for (int r = 0; r < 8; ++r) {
        float v = __ldg(x + xoff + r * NN);
        xv[0][r] = pack2(v, v);
    }

    for (int tile = bx; tile < NTILES; tile += GRID) {
        // next tile's x offset (clamped; loads in-bounds, values unused at end)
        const int tn = (tile + GRID < NTILES) ? (tile + GRID) : tile;
        const uint32_t rbn = (uint32_t)tn * 16 + g * 8;
        const uint32_t xoffn = ((rbn >> 9) * (CI * FF) + (rbn & (FF - 1))) * NN + lane;

        uint64_t acc[8][4];
#pragma unroll
        for (int cc = 0; cc < 4; ++cc)
#pragma unroll
            for (int r = 0; r < 8; ++r) acc[r][cc] = bp[cc];

#pragma unroll
        for (int i = 0; i < CI; ++i) {
            uint64_t w[4];
#pragma unroll
            for (int cc = 0; cc < 4; ++cc)
                w[cc] = wbase[(i * CO + cc) * NN];

            // prefetch i+1 into slot (i+1)&1; at i=15 fetch next tile's i=0
            {
                const uint32_t po = (i < CI - 1)
                                  ? (xoff + (uint32_t)(i + 1) * (FF * NN))
                                  : xoffn;
#pragma unroll
                for (int r = 0; r < 8; ++r) {
                    float v = __ldg(x + po + r * NN);
                    xv[(i + 1) & 1][r] = pack2(v, v);
                }
            }

#pragma unroll
            for (int cc = 0; cc < 4; ++cc)
#pragma unroll
                for (int r = 0; r < 8; ++r)
                    ffma2(acc[r][cc], xv[i & 1][r], w[cc]);
        }

        // out[b, c0+cc, f+r, 2n+k] as u64 — coalesced 256B streaming stores
        const uint32_t rb = (uint32_t)tile * 16 + g * 8;
        uint64_t* op = (uint64_t*)out
                     + ((size_t)((rb >> 9) * CO + c0) * FF + (rb & (FF - 1))) * NN + lane;
#pragma unroll
        for (int cc = 0; cc < 4; ++cc)
#pragma unroll
            for (int r = 0; r < 8; ++r)
                stcs64(op + ((size_t)cc * FF + r) * NN, acc[r][cc]);

        xoff = xoffn;
    }
}

// ---------------------------------------------------------------------------
extern "C" void kernel_launch(void* const* d_in, const int* in_sizes, int n_in,
                              void* d_out, int out_size)
{
    const float* x  = (const float*)d_in[0];
    const float* W1 = (const float*)d_in[1];
    const float* b1 = (const float*)d_in[2];
    const float* W2 = (const float*)d_in[3];
    const float* b2 = (const float*)d_in[4];
    float* out = (float*)d_out;

    cudaFuncSetAttribute(up_kernel, cudaFuncAttributeMaxDynamicSharedMemorySize,
                         SMEM_BYTES);
    up_kernel<<<GRID, 256, SMEM_BYTES>>>(x, W1, b1, W2, b2, out);
}